// round 11
// baseline (speedup 1.0000x reference)
#include <cuda_runtime.h>
#include <math.h>

#define BATCH 2
#define DIM   48
#define HEADS 8
#define CPH   6
#define HH    384
#define WW    384
#define NPIX  (HH*WW)

#define PXB 384          // pixels per pw block
#define PXS 392          // padded smem stride (floats); conflict-free B loads

// ---------------- scratch ----------------
__device__ float g_pwq [BATCH*DIM*NPIX];      // 56.6 MB
__device__ float g_pwkv[BATCH*2*DIM*NPIX];    // 113 MB (k: 0..47, v: 48..95)
__device__ float g_v   [BATCH*DIM*NPIX];      // 56.6 MB
__device__ float g_acc [BATCH*HEADS*48];
__device__ float g_meff[BATCH*DIM*DIM];

// ---------------- helpers ----------------
__device__ __forceinline__ void cpa16(unsigned int dst, const float* src){
    asm volatile("cp.async.cg.shared.global [%0], [%1], 16;" :: "r"(dst), "l"(src) : "memory");
}
__device__ __forceinline__ void cpa_commit(){
    asm volatile("cp.async.commit_group;" ::: "memory");
}
template<int N>
__device__ __forceinline__ void cpa_wait(){
    asm volatile("cp.async.wait_group %0;" :: "n"(N) : "memory");
}
__device__ __forceinline__ unsigned int f2tf32(float x){
    unsigned int u;
    asm("cvt.rna.tf32.f32 %0, %1;" : "=r"(u) : "f"(x));
    return u;
}
__device__ __forceinline__ void mma_tf32(float* d,
                                         const unsigned int* a,
                                         unsigned int b0, unsigned int b1){
    asm volatile(
        "mma.sync.aligned.m16n8k8.row.col.f32.tf32.tf32.f32 "
        "{%0,%1,%2,%3}, {%4,%5,%6,%7}, {%8,%9}, {%0,%1,%2,%3};"
        : "+f"(d[0]), "+f"(d[1]), "+f"(d[2]), "+f"(d[3])
        : "r"(a[0]), "r"(a[1]), "r"(a[2]), "r"(a[3]), "r"(b0), "r"(b1));
}

// Upfront-window depthwise conv (global-memory, scalar — v branch)
template<int R>
__device__ __forceinline__ void winconv(const float* __restrict__ chan, int x,
                                        bool xm, bool xp, int ytop, bool fast,
                                        const float* __restrict__ wr, float* out){
    float v[R][3];
    if (fast){
        const float* rp = chan + (size_t)ytop*WW + x;
        #pragma unroll
        for (int r = 0; r < R; r++){
            v[r][0] = __ldg(rp + r*WW - 1);
            v[r][1] = __ldg(rp + r*WW    );
            v[r][2] = __ldg(rp + r*WW + 1);
        }
    } else {
        int xl = max(x-1, 0), xr = min(x+1, WW-1);
        #pragma unroll
        for (int r = 0; r < R; r++){
            int yy = ytop + r; bool yok = (yy >= 0 && yy < HH);
            const float* rp = chan + (size_t)(yok ? yy : 0)*WW;
            v[r][0] = (yok && xm) ? __ldg(rp + xl) : 0.f;
            v[r][1] =  yok        ? __ldg(rp + x ) : 0.f;
            v[r][2] = (yok && xp) ? __ldg(rp + xr) : 0.f;
        }
    }
    #pragma unroll
    for (int i = 0; i < R-2; i++){
        out[i] = wr[0]*v[i  ][0] + wr[1]*v[i  ][1] + wr[2]*v[i  ][2]
               + wr[3]*v[i+1][0] + wr[4]*v[i+1][1] + wr[5]*v[i+1][2]
               + wr[6]*v[i+2][0] + wr[7]*v[i+2][1] + wr[8]*v[i+2][2];
    }
}

// Vectorized 1-row x 4-col depthwise window: one LDG.128 per row + SHFL halos.
// c0 = col of m.x (16B aligned). Edge lanes (0,31) fetch their halo scalar.
__device__ __forceinline__ void winconv4(const float* __restrict__ chan,
                                         int c0, int lane, int x0, int ytop,
                                         const float* __restrict__ wr, float* o){
    float4 m[3]; float ed[3];
    #pragma unroll
    for (int r = 0; r < 3; r++){
        int yy = ytop + r;
        bool yok = (yy >= 0 && yy < HH);
        const float* rp = chan + (size_t)(yok ? yy : 0)*WW;
        m[r] = yok ? __ldg(reinterpret_cast<const float4*>(rp + c0))
                   : make_float4(0.f, 0.f, 0.f, 0.f);
        int ec  = (lane == 0) ? (c0 - 1) : (x0 + 128);
        bool eok = yok && ((lane == 0 && ec >= 0) || (lane == 31 && ec < WW));
        ed[r] = eok ? __ldg(rp + ec) : 0.f;
    }
    o[0] = o[1] = o[2] = o[3] = 0.f;
    #pragma unroll
    for (int r = 0; r < 3; r++){
        float lft = __shfl_up_sync  (0xffffffffu, m[r].w, 1);
        float rgt = __shfl_down_sync(0xffffffffu, m[r].x, 1);
        if (lane == 0)  lft = ed[r];
        if (lane == 31) rgt = ed[r];
        float w0 = wr[r*3+0], w1 = wr[r*3+1], w2 = wr[r*3+2];
        o[0] += w0*lft    + w1*m[r].x + w2*m[r].y;
        o[1] += w0*m[r].x + w1*m[r].y + w2*m[r].z;
        o[2] += w0*m[r].y + w1*m[r].z + w2*m[r].w;
        o[3] += w0*m[r].z + w1*m[r].w + w2*rgt;
    }
}

// ---------------- kernels ----------------
__global__ void zero_acc_kernel(){
    int t = blockIdx.x*blockDim.x + threadIdx.x;
    if (t < BATCH*HEADS*48) g_acc[t] = 0.f;
}

// 48-oc tf32 pw GEMM (evs pw + final out-GEMM). Unchanged from R10.
__global__ __launch_bounds__(384, 2) void pw_mma_kernel(const float* __restrict__ in,
                                                        const float* __restrict__ W,
                                                        float* __restrict__ out,
                                                        int inBC, int outBC,
                                                        int wStride){
    extern __shared__ float dsm[];
    float* xs = dsm;                                           // 48 x PXS
    unsigned int* wsm = (unsigned int*)(dsm + 48*PXS);         // 48 x 49

    const int tid = threadIdx.x;
    const int b   = blockIdx.y;
    const float* Wb = W + b*wStride;

    const int base = blockIdx.x*PXB;
    const float* inp = in + (size_t)b*inBC*NPIX + base;
    const unsigned int xsu = (unsigned int)__cvta_generic_to_shared(xs);
    #pragma unroll
    for (int r = 0; r < 12; r++){
        int e  = tid + r*384;
        int ic = e/96, q = e%96;
        cpa16(xsu + (unsigned int)((ic*PXS + q*4)*4),
              inp + (size_t)ic*NPIX + q*4);
    }
    cpa_commit();

    #pragma unroll
    for (int r = 0; r < 6; r++){
        int t = tid + r*384;
        int oc = t/48, ic = t%48;
        wsm[oc*49 + ic] = f2tf32(Wb[t]);
    }

    cpa_wait<0>();
    __syncthreads();

    const int w    = tid >> 5;
    const int lane = tid & 31;
    const int mt   = w % 3;
    const int ng   = w / 3;
    const int gid  = lane >> 2;
    const int tig  = lane & 3;

    unsigned int a[6][4];
    #pragma unroll
    for (int ks = 0; ks < 6; ks++){
        int r0 = mt*16 + gid, k0 = ks*8 + tig;
        a[ks][0] = wsm[ r0     *49 + k0    ];
        a[ks][1] = wsm[(r0 + 8)*49 + k0    ];
        a[ks][2] = wsm[ r0     *49 + k0 + 4];
        a[ks][3] = wsm[(r0 + 8)*49 + k0 + 4];
    }

    float* op = out + (size_t)b*outBC*NPIX + base;
    const int r0 = mt*16 + gid;

    #pragma unroll
    for (int i = 0; i < 12; i++){
        const int px0 = (ng*12 + i)*8;
        float d[4] = {0.f, 0.f, 0.f, 0.f};
        #pragma unroll
        for (int ks = 0; ks < 6; ks++){
            unsigned int b0 = f2tf32(xs[(ks*8 + tig    )*PXS + px0 + gid]);
            unsigned int b1 = f2tf32(xs[(ks*8 + tig + 4)*PXS + px0 + gid]);
            mma_tf32(d, a[ks], b0, b1);
        }
        *reinterpret_cast<float2*>(op + (size_t)r0*NPIX     + px0 + tig*2) = make_float2(d[0], d[1]);
        *reinterpret_cast<float2*>(op + (size_t)(r0+8)*NPIX + px0 + tig*2) = make_float2(d[2], d[3]);
    }
}

// 96-oc fused img pointwise: k+v in one pass (img staged once).
// 12 warps = 6 m-tiles (16 oc) x 2 n-groups (192 px, 24 n-tiles each).
__global__ __launch_bounds__(384, 2) void pw_mma96_kernel(const float* __restrict__ in,
                                                          const float* __restrict__ W,
                                                          float* __restrict__ out){
    extern __shared__ float dsm[];
    float* xs = dsm;                                           // 48 x PXS
    unsigned int* wsm = (unsigned int*)(dsm + 48*PXS);         // 96 x 49

    const int tid = threadIdx.x;
    const int b   = blockIdx.y;

    const int base = blockIdx.x*PXB;
    const float* inp = in + (size_t)b*DIM*NPIX + base;
    const unsigned int xsu = (unsigned int)__cvta_generic_to_shared(xs);
    #pragma unroll
    for (int r = 0; r < 12; r++){
        int e  = tid + r*384;
        int ic = e/96, q = e%96;
        cpa16(xsu + (unsigned int)((ic*PXS + q*4)*4),
              inp + (size_t)ic*NPIX + q*4);
    }
    cpa_commit();

    #pragma unroll
    for (int r = 0; r < 12; r++){
        int t = tid + r*384;
        int oc = t/48, ic = t%48;
        wsm[oc*49 + ic] = f2tf32(W[t]);
    }

    cpa_wait<0>();
    __syncthreads();

    const int w    = tid >> 5;
    const int lane = tid & 31;
    const int mt   = w >> 1;       // 0..5 -> 96 oc
    const int ng   = w & 1;        // 2 n-groups of 192 px
    const int gid  = lane >> 2;
    const int tig  = lane & 3;

    unsigned int a[6][4];
    #pragma unroll
    for (int ks = 0; ks < 6; ks++){
        int r0 = mt*16 + gid, k0 = ks*8 + tig;
        a[ks][0] = wsm[ r0     *49 + k0    ];
        a[ks][1] = wsm[(r0 + 8)*49 + k0    ];
        a[ks][2] = wsm[ r0     *49 + k0 + 4];
        a[ks][3] = wsm[(r0 + 8)*49 + k0 + 4];
    }

    float* op = out + (size_t)b*2*DIM*NPIX + base;
    const int r0 = mt*16 + gid;

    #pragma unroll
    for (int i = 0; i < 24; i++){
        const int px0 = (ng*24 + i)*8;
        float d[4] = {0.f, 0.f, 0.f, 0.f};
        #pragma unroll
        for (int ks = 0; ks < 6; ks++){
            unsigned int b0 = f2tf32(xs[(ks*8 + tig    )*PXS + px0 + gid]);
            unsigned int b1 = f2tf32(xs[(ks*8 + tig + 4)*PXS + px0 + gid]);
            mma_tf32(d, a[ks], b0, b1);
        }
        *reinterpret_cast<float2*>(op + (size_t)r0*NPIX     + px0 + tig*2) = make_float2(d[0], d[1]);
        *reinterpret_cast<float2*>(op + (size_t)(r0+8)*NPIX + px0 + tig*2) = make_float2(d[2], d[3]);
    }
}

// q,k depthwise 3x3 + Gram/norm — vectorized windows.
// Block: 128 cols x 32 rows; warp w owns rows w*4..w*4+3 (1 row/iter, 4 iters).
// Thread: 4 columns via LDG.128 + SHFL halos.
__global__ __launch_bounds__(256, 2) void qk_gram_kernel(const float* __restrict__ Wq2,
                                                         const float* __restrict__ Wkv2){
    __shared__ float wq[CPH*9], wk[CPH*9];
    __shared__ float accs[48];
    const int tid = threadIdx.x;
    const int bh  = blockIdx.z;
    const int b   = bh >> 3, h = bh & 7;
    if (tid < CPH*9){
        int c6 = tid/9, t = tid%9;
        wq[tid] = Wq2[(h*CPH + c6)*27 + 9 + t];
    } else if (tid >= 64 && tid < 64 + CPH*9){
        int e = tid - 64, c6 = e/9, t = e%9;
        wk[e] = Wkv2[(h*CPH + c6)*27 + 9 + t];
    } else if (tid >= 128 && tid < 176){
        accs[tid - 128] = 0.f;
    }
    __syncthreads();

    const int lane = tid & 31;
    const int w    = tid >> 5;
    const int x0   = blockIdx.x*128;
    const int c0   = x0 + 4*lane;
    const int y0   = blockIdx.y*32;

    const float* qbase = g_pwq  + (size_t)b*DIM*NPIX   + (size_t)h*CPH*NPIX;
    const float* kbase = g_pwkv + (size_t)b*2*DIM*NPIX + (size_t)h*CPH*NPIX;

    float G[36], qn[CPH], kn[CPH];
    #pragma unroll
    for (int i = 0; i < 36; i++) G[i] = 0.f;
    #pragma unroll
    for (int i = 0; i < CPH; i++){ qn[i] = 0.f; kn[i] = 0.f; }

    #pragma unroll 1
    for (int t = 0; t < 4; t++){
        const int ytop = y0 + w*4 + t - 1;

        float ka[CPH][4];
        #pragma unroll
        for (int c6 = 0; c6 < CPH; c6++){
            float o[4];
            winconv4(kbase + (size_t)c6*NPIX, c0, lane, x0, ytop, &wk[c6*9], o);
            #pragma unroll
            for (int j = 0; j < 4; j++){ ka[c6][j] = o[j]; kn[c6] += o[j]*o[j]; }
        }
        #pragma unroll
        for (int c6 = 0; c6 < CPH; c6++){
            float o[4];
            winconv4(qbase + (size_t)c6*NPIX, c0, lane, x0, ytop, &wq[c6*9], o);
            #pragma unroll
            for (int j = 0; j < 4; j++) qn[c6] += o[j]*o[j];
            #pragma unroll
            for (int d6 = 0; d6 < CPH; d6++)
                G[c6*CPH + d6] += o[0]*ka[d6][0] + o[1]*ka[d6][1]
                                + o[2]*ka[d6][2] + o[3]*ka[d6][3];
        }
    }

    #pragma unroll
    for (int j = 0; j < 36; j++){
        float v = G[j];
        #pragma unroll
        for (int o = 16; o; o >>= 1) v += __shfl_xor_sync(0xffffffffu, v, o);
        if (lane == 0) atomicAdd(&accs[j], v);
    }
    #pragma unroll
    for (int j = 0; j < CPH; j++){
        float v = qn[j];
        #pragma unroll
        for (int o = 16; o; o >>= 1) v += __shfl_xor_sync(0xffffffffu, v, o);
        if (lane == 0) atomicAdd(&accs[36 + j], v);
        float u = kn[j];
        #pragma unroll
        for (int o = 16; o; o >>= 1) u += __shfl_xor_sync(0xffffffffu, u, o);
        if (lane == 0) atomicAdd(&accs[42 + j], u);
    }
    __syncthreads();
    if (tid < 48) atomicAdd(&g_acc[(b*HEADS + h)*48 + tid], accs[tid]);
}

// softmax + fold Wout -> Meff[b] (48x48)
__global__ void attn_kernel(const float* __restrict__ Wout,
                            const float* __restrict__ temp){
    __shared__ float attn_s[BATCH*HEADS*36];
    int t = threadIdx.x;
    if (t < BATCH*HEADS*CPH){
        int b  = t/(HEADS*CPH);
        int h  = (t/CPH)%HEADS;
        int c6 = t%CPH;
        const float* a = g_acc + (b*HEADS + h)*48;
        float qnorm = fmaxf(sqrtf(a[36 + c6]), 1e-12f);
        float s[CPH];
        float mx = -1e30f;
        #pragma unroll
        for (int d6 = 0; d6 < CPH; d6++){
            float knorm = fmaxf(sqrtf(a[42 + d6]), 1e-12f);
            float v = a[c6*CPH + d6] / (qnorm*knorm) * temp[h];
            s[d6] = v; mx = fmaxf(mx, v);
        }
        float sum = 0.f;
        #pragma unroll
        for (int d6 = 0; d6 < CPH; d6++){ s[d6] = expf(s[d6]-mx); sum += s[d6]; }
        float inv = 1.f/sum;
        #pragma unroll
        for (int d6 = 0; d6 < CPH; d6++)
            attn_s[(b*HEADS + h)*36 + c6*CPH + d6] = s[d6]*inv;
    }
    __syncthreads();
    for (int e = t; e < BATCH*DIM*DIM; e += blockDim.x){
        int b = e/(DIM*DIM), rem = e%(DIM*DIM), o = rem/DIM, d = rem%DIM;
        int h = d/CPH, d6 = d%CPH;
        float s = 0.f;
        #pragma unroll
        for (int c6 = 0; c6 < CPH; c6++)
            s += Wout[o*DIM + h*CPH + c6] * attn_s[(b*HEADS + h)*36 + c6*CPH + d6];
        g_meff[e] = s;
    }
}

// depthwise 3x3 for v channels -> g_v (unchanged)
__global__ __launch_bounds__(256, 2) void v_conv_kernel(const float* __restrict__ Wkv2){
    __shared__ float wv[DIM*9];
    const int tid = threadIdx.x;
    for (int t = tid; t < DIM*9; t += 256)
        wv[t] = Wkv2[(DIM + t/9)*27 + 9 + (t%9)];
    __syncthreads();

    const int lane = tid & 31;
    const int w    = tid >> 5;
    const int b    = blockIdx.z;
    const int x0   = blockIdx.x*32;
    const int x    = x0 + lane;
    const int yb   = blockIdx.y*8;
    const bool xm = (x > 0), xp = (x < WW-1);
    const bool fast = (x0 > 0) && (x0 + 32 < WW) && (yb > 0) && (yb + 9 < HH);

    const float* vbase = g_pwkv + (size_t)b*2*DIM*NPIX + (size_t)DIM*NPIX;
    float* vo = g_v + (size_t)b*DIM*NPIX;
    #pragma unroll
    for (int c6 = 0; c6 < CPH; c6++){
        int c = w*CPH + c6;
        float o[8];
        winconv<10>(vbase + (size_t)c*NPIX, x, xm, xp, yb - 1, fast, &wv[c*9], o);
        #pragma unroll
        for (int i = 0; i < 8; i++)
            vo[(size_t)c*NPIX + (size_t)(yb + i)*WW + x] = o[i];
    }
}

// ---------------- launch ----------------
extern "C" void kernel_launch(void* const* d_in, const int* in_sizes, int n_in,
                              void* d_out, int out_size){
    const float* img  = (const float*)d_in[0];
    const float* evs  = (const float*)d_in[1];
    const float* Wq1  = (const float*)d_in[2];
    const float* Wq2  = (const float*)d_in[3];
    const float* Wkv1 = (const float*)d_in[4];
    const float* Wkv2 = (const float*)d_in[5];
    const float* Wout = (const float*)d_in[6];
    const float* temp = (const float*)d_in[7];
    float* out = (float*)d_out;

    float *pwq, *pwkv, *vbuf, *meff;
    cudaGetSymbolAddress((void**)&pwq,  g_pwq);
    cudaGetSymbolAddress((void**)&pwkv, g_pwkv);
    cudaGetSymbolAddress((void**)&vbuf, g_v);
    cudaGetSymbolAddress((void**)&meff, g_meff);

    static cudaStream_t s2 = nullptr;
    static cudaEvent_t  evF = nullptr, evK = nullptr, evV = nullptr;
    if (s2 == nullptr){
        cudaStreamCreateWithFlags(&s2, cudaStreamNonBlocking);
        cudaEventCreateWithFlags(&evF, cudaEventDisableTiming);
        cudaEventCreateWithFlags(&evK, cudaEventDisableTiming);
        cudaEventCreateWithFlags(&evV, cudaEventDisableTiming);
    }

    const int smem_pw   = (48*PXS + 48*49)*4;   // 84,672 B
    const int smem_pw96 = (48*PXS + 96*49)*4;   // 94,080 B
    cudaFuncSetAttribute(pw_mma_kernel,   cudaFuncAttributeMaxDynamicSharedMemorySize, smem_pw);
    cudaFuncSetAttribute(pw_mma96_kernel, cudaFuncAttributeMaxDynamicSharedMemorySize, smem_pw96);

    zero_acc_kernel<<<3, 256>>>();

    cudaEventRecord(evF, 0);
    cudaStreamWaitEvent(s2, evF, 0);

    dim3 gpw(NPIX/PXB, BATCH);
    // stream B: fused 96-oc img pointwise (k+v), then v depthwise conv
    pw_mma96_kernel<<<gpw, 384, smem_pw96, s2>>>(img, Wkv1, pwkv);
    cudaEventRecord(evK, s2);
    dim3 gvc(WW/32, HH/8, BATCH);
    v_conv_kernel<<<gvc, 256, 0, s2>>>(Wkv2);
    cudaEventRecord(evV, s2);

    // main: evs pw, then qk (needs k), attn, final GEMM (needs g_v)
    pw_mma_kernel<<<gpw, 384, smem_pw>>>(evs, Wq1, pwq, DIM, DIM, 0);
    cudaStreamWaitEvent(0, evK, 0);

    dim3 gqk(WW/128, HH/32, BATCH*HEADS);
    qk_gram_kernel<<<gqk, 256>>>(Wq2, Wkv2);

    attn_kernel<<<1, 256>>>(Wout, temp);

    cudaStreamWaitEvent(0, evV, 0);
    pw_mma_kernel<<<gpw, 384, smem_pw>>>(vbuf, meff, out, DIM, DIM, DIM*DIM);
}

// round 12
// speedup vs baseline: 1.0708x; 1.0708x over previous
#include <cuda_runtime.h>
#include <math.h>

#define BATCH 2
#define DIM   48
#define HEADS 8
#define CPH   6
#define HH    384
#define WW    384
#define NPIX  (HH*WW)

#define PXB 384          // pixels per pw block
#define PXS 392          // padded smem stride (floats); conflict-free B loads

// ---------------- scratch ----------------
__device__ float g_pwq [BATCH*DIM*NPIX];      // 56.6 MB
__device__ float g_pwkv[BATCH*2*DIM*NPIX];    // 113 MB (k: 0..47, v: 48..95)
__device__ float g_v   [BATCH*DIM*NPIX];      // 56.6 MB
__device__ float g_acc [BATCH*HEADS*48];
__device__ float g_meff[BATCH*DIM*DIM];

// ---------------- helpers ----------------
__device__ __forceinline__ void cpa16(unsigned int dst, const float* src){
    asm volatile("cp.async.cg.shared.global [%0], [%1], 16;" :: "r"(dst), "l"(src) : "memory");
}
__device__ __forceinline__ void cpa_commit(){
    asm volatile("cp.async.commit_group;" ::: "memory");
}
template<int N>
__device__ __forceinline__ void cpa_wait(){
    asm volatile("cp.async.wait_group %0;" :: "n"(N) : "memory");
}
__device__ __forceinline__ unsigned int f2tf32(float x){
    unsigned int u;
    asm("cvt.rna.tf32.f32 %0, %1;" : "=r"(u) : "f"(x));
    return u;
}
__device__ __forceinline__ void mma_tf32(float* d,
                                         const unsigned int* a,
                                         unsigned int b0, unsigned int b1){
    asm volatile(
        "mma.sync.aligned.m16n8k8.row.col.f32.tf32.tf32.f32 "
        "{%0,%1,%2,%3}, {%4,%5,%6,%7}, {%8,%9}, {%0,%1,%2,%3};"
        : "+f"(d[0]), "+f"(d[1]), "+f"(d[2]), "+f"(d[3])
        : "r"(a[0]), "r"(a[1]), "r"(a[2]), "r"(a[3]), "r"(b0), "r"(b1));
}

// Upfront-window depthwise conv (global-memory, scalar)
template<int R>
__device__ __forceinline__ void winconv(const float* __restrict__ chan, int x,
                                        bool xm, bool xp, int ytop, bool fast,
                                        const float* __restrict__ wr, float* out){
    float v[R][3];
    if (fast){
        const float* rp = chan + (size_t)ytop*WW + x;
        #pragma unroll
        for (int r = 0; r < R; r++){
            v[r][0] = __ldg(rp + r*WW - 1);
            v[r][1] = __ldg(rp + r*WW    );
            v[r][2] = __ldg(rp + r*WW + 1);
        }
    } else {
        int xl = max(x-1, 0), xr = min(x+1, WW-1);
        #pragma unroll
        for (int r = 0; r < R; r++){
            int yy = ytop + r; bool yok = (yy >= 0 && yy < HH);
            const float* rp = chan + (size_t)(yok ? yy : 0)*WW;
            v[r][0] = (yok && xm) ? __ldg(rp + xl) : 0.f;
            v[r][1] =  yok        ? __ldg(rp + x ) : 0.f;
            v[r][2] = (yok && xp) ? __ldg(rp + xr) : 0.f;
        }
    }
    #pragma unroll
    for (int i = 0; i < R-2; i++){
        out[i] = wr[0]*v[i  ][0] + wr[1]*v[i  ][1] + wr[2]*v[i  ][2]
               + wr[3]*v[i+1][0] + wr[4]*v[i+1][1] + wr[5]*v[i+1][2]
               + wr[6]*v[i+2][0] + wr[7]*v[i+2][1] + wr[8]*v[i+2][2];
    }
}

// ---------------- kernels ----------------
__global__ void zero_acc_kernel(){
    int t = blockIdx.x*blockDim.x + threadIdx.x;
    if (t < BATCH*HEADS*48) g_acc[t] = 0.f;
}

// 48-oc tf32 pw GEMM (evs pw + final out-GEMM).
__global__ __launch_bounds__(384, 2) void pw_mma_kernel(const float* __restrict__ in,
                                                        const float* __restrict__ W,
                                                        float* __restrict__ out,
                                                        int inBC, int outBC,
                                                        int wStride){
    extern __shared__ float dsm[];
    float* xs = dsm;                                           // 48 x PXS
    unsigned int* wsm = (unsigned int*)(dsm + 48*PXS);         // 48 x 49

    const int tid = threadIdx.x;
    const int b   = blockIdx.y;
    const float* Wb = W + b*wStride;

    const int base = blockIdx.x*PXB;
    const float* inp = in + (size_t)b*inBC*NPIX + base;
    const unsigned int xsu = (unsigned int)__cvta_generic_to_shared(xs);
    #pragma unroll
    for (int r = 0; r < 12; r++){
        int e  = tid + r*384;
        int ic = e/96, q = e%96;
        cpa16(xsu + (unsigned int)((ic*PXS + q*4)*4),
              inp + (size_t)ic*NPIX + q*4);
    }
    cpa_commit();

    #pragma unroll
    for (int r = 0; r < 6; r++){
        int t = tid + r*384;
        int oc = t/48, ic = t%48;
        wsm[oc*49 + ic] = f2tf32(Wb[t]);
    }

    cpa_wait<0>();
    __syncthreads();

    const int w    = tid >> 5;
    const int lane = tid & 31;
    const int mt   = w % 3;
    const int ng   = w / 3;
    const int gid  = lane >> 2;
    const int tig  = lane & 3;

    unsigned int a[6][4];
    #pragma unroll
    for (int ks = 0; ks < 6; ks++){
        int r0 = mt*16 + gid, k0 = ks*8 + tig;
        a[ks][0] = wsm[ r0     *49 + k0    ];
        a[ks][1] = wsm[(r0 + 8)*49 + k0    ];
        a[ks][2] = wsm[ r0     *49 + k0 + 4];
        a[ks][3] = wsm[(r0 + 8)*49 + k0 + 4];
    }

    float* op = out + (size_t)b*outBC*NPIX + base;
    const int r0 = mt*16 + gid;

    #pragma unroll
    for (int i = 0; i < 12; i++){
        const int px0 = (ng*12 + i)*8;
        float d[4] = {0.f, 0.f, 0.f, 0.f};
        #pragma unroll
        for (int ks = 0; ks < 6; ks++){
            unsigned int b0 = f2tf32(xs[(ks*8 + tig    )*PXS + px0 + gid]);
            unsigned int b1 = f2tf32(xs[(ks*8 + tig + 4)*PXS + px0 + gid]);
            mma_tf32(d, a[ks], b0, b1);
        }
        *reinterpret_cast<float2*>(op + (size_t)r0*NPIX     + px0 + tig*2) = make_float2(d[0], d[1]);
        *reinterpret_cast<float2*>(op + (size_t)(r0+8)*NPIX + px0 + tig*2) = make_float2(d[2], d[3]);
    }
}

// 96-oc fused img pointwise: k+v in one pass (img staged once).
__global__ __launch_bounds__(384, 2) void pw_mma96_kernel(const float* __restrict__ in,
                                                          const float* __restrict__ W,
                                                          float* __restrict__ out){
    extern __shared__ float dsm[];
    float* xs = dsm;                                           // 48 x PXS
    unsigned int* wsm = (unsigned int*)(dsm + 48*PXS);         // 96 x 49

    const int tid = threadIdx.x;
    const int b   = blockIdx.y;

    const int base = blockIdx.x*PXB;
    const float* inp = in + (size_t)b*DIM*NPIX + base;
    const unsigned int xsu = (unsigned int)__cvta_generic_to_shared(xs);
    #pragma unroll
    for (int r = 0; r < 12; r++){
        int e  = tid + r*384;
        int ic = e/96, q = e%96;
        cpa16(xsu + (unsigned int)((ic*PXS + q*4)*4),
              inp + (size_t)ic*NPIX + q*4);
    }
    cpa_commit();

    #pragma unroll
    for (int r = 0; r < 12; r++){
        int t = tid + r*384;
        int oc = t/48, ic = t%48;
        wsm[oc*49 + ic] = f2tf32(W[t]);
    }

    cpa_wait<0>();
    __syncthreads();

    const int w    = tid >> 5;
    const int lane = tid & 31;
    const int mt   = w >> 1;       // 0..5 -> 96 oc
    const int ng   = w & 1;        // 2 n-groups of 192 px
    const int gid  = lane >> 2;
    const int tig  = lane & 3;

    unsigned int a[6][4];
    #pragma unroll
    for (int ks = 0; ks < 6; ks++){
        int r0 = mt*16 + gid, k0 = ks*8 + tig;
        a[ks][0] = wsm[ r0     *49 + k0    ];
        a[ks][1] = wsm[(r0 + 8)*49 + k0    ];
        a[ks][2] = wsm[ r0     *49 + k0 + 4];
        a[ks][3] = wsm[(r0 + 8)*49 + k0 + 4];
    }

    float* op = out + (size_t)b*2*DIM*NPIX + base;
    const int r0 = mt*16 + gid;

    #pragma unroll
    for (int i = 0; i < 24; i++){
        const int px0 = (ng*24 + i)*8;
        float d[4] = {0.f, 0.f, 0.f, 0.f};
        #pragma unroll
        for (int ks = 0; ks < 6; ks++){
            unsigned int b0 = f2tf32(xs[(ks*8 + tig    )*PXS + px0 + gid]);
            unsigned int b1 = f2tf32(xs[(ks*8 + tig + 4)*PXS + px0 + gid]);
            mma_tf32(d, a[ks], b0, b1);
        }
        *reinterpret_cast<float2*>(op + (size_t)r0*NPIX     + px0 + tig*2) = make_float2(d[0], d[1]);
        *reinterpret_cast<float2*>(op + (size_t)(r0+8)*NPIX + px0 + tig*2) = make_float2(d[2], d[3]);
    }
}

// q,k depthwise 3x3 + Gram/norm. One (b,h) per block; block covers 32x128 px.
// (PROTECTED R5/R10 version — row-reuse winconv<6>, one reduce per block)
__global__ __launch_bounds__(256, 2) void qk_gram_kernel(const float* __restrict__ Wq2,
                                                         const float* __restrict__ Wkv2){
    __shared__ float wq[CPH*9], wk[CPH*9];
    __shared__ float accs[48];
    const int tid = threadIdx.x;
    const int bh  = blockIdx.z;
    const int b   = bh >> 3, h = bh & 7;
    if (tid < CPH*9){
        int c6 = tid/9, t = tid%9;
        wq[tid] = Wq2[(h*CPH + c6)*27 + 9 + t];
    } else if (tid >= 64 && tid < 64 + CPH*9){
        int e = tid - 64, c6 = e/9, t = e%9;
        wk[e] = Wkv2[(h*CPH + c6)*27 + 9 + t];
    } else if (tid >= 128 && tid < 176){
        accs[tid - 128] = 0.f;
    }
    __syncthreads();

    const int lane = tid & 31;
    const int w    = tid >> 5;
    const int x0   = blockIdx.x*32;
    const int x    = x0 + lane;
    const bool xm = (x > 0), xp = (x < WW-1);
    const bool xfast = (x0 > 0) && (x0 + 32 < WW);

    const float* qbase = g_pwq  + (size_t)b*DIM*NPIX   + (size_t)h*CPH*NPIX;
    const float* kbase = g_pwkv + (size_t)b*2*DIM*NPIX + (size_t)h*CPH*NPIX;

    float G[36], qn[CPH], kn[CPH];
    #pragma unroll
    for (int i = 0; i < 36; i++) G[i] = 0.f;
    #pragma unroll
    for (int i = 0; i < CPH; i++){ qn[i] = 0.f; kn[i] = 0.f; }

    #pragma unroll 1
    for (int t4 = 0; t4 < 4; t4++){
        const int y0   = blockIdx.y*128 + t4*32 + w*4;
        const int ytop = y0 - 1;
        const bool fast = xfast && (ytop >= 0) && (ytop + 5 < HH);

        float ka[CPH][4];
        #pragma unroll
        for (int c6 = 0; c6 < CPH; c6++){
            float o[4];
            winconv<6>(kbase + (size_t)c6*NPIX, x, xm, xp, ytop, fast, &wk[c6*9], o);
            #pragma unroll
            for (int i = 0; i < 4; i++){ ka[c6][i] = o[i]; kn[c6] += o[i]*o[i]; }
        }
        #pragma unroll
        for (int c6 = 0; c6 < CPH; c6++){
            float o[4];
            winconv<6>(qbase + (size_t)c6*NPIX, x, xm, xp, ytop, fast, &wq[c6*9], o);
            #pragma unroll
            for (int i = 0; i < 4; i++) qn[c6] += o[i]*o[i];
            #pragma unroll
            for (int d6 = 0; d6 < CPH; d6++)
                G[c6*CPH + d6] += o[0]*ka[d6][0] + o[1]*ka[d6][1]
                                + o[2]*ka[d6][2] + o[3]*ka[d6][3];
        }
    }

    #pragma unroll
    for (int j = 0; j < 36; j++){
        float v = G[j];
        #pragma unroll
        for (int o = 16; o; o >>= 1) v += __shfl_xor_sync(0xffffffffu, v, o);
        if (lane == 0) atomicAdd(&accs[j], v);
    }
    #pragma unroll
    for (int j = 0; j < CPH; j++){
        float v = qn[j];
        #pragma unroll
        for (int o = 16; o; o >>= 1) v += __shfl_xor_sync(0xffffffffu, v, o);
        if (lane == 0) atomicAdd(&accs[36 + j], v);
        float u = kn[j];
        #pragma unroll
        for (int o = 16; o; o >>= 1) u += __shfl_xor_sync(0xffffffffu, u, o);
        if (lane == 0) atomicAdd(&accs[42 + j], u);
    }
    __syncthreads();
    if (tid < 48) atomicAdd(&g_acc[(b*HEADS + h)*48 + tid], accs[tid]);
}

// softmax + fold Wout -> Meff[b] (48x48)
__global__ void attn_kernel(const float* __restrict__ Wout,
                            const float* __restrict__ temp){
    __shared__ float attn_s[BATCH*HEADS*36];
    int t = threadIdx.x;
    if (t < BATCH*HEADS*CPH){
        int b  = t/(HEADS*CPH);
        int h  = (t/CPH)%HEADS;
        int c6 = t%CPH;
        const float* a = g_acc + (b*HEADS + h)*48;
        float qnorm = fmaxf(sqrtf(a[36 + c6]), 1e-12f);
        float s[CPH];
        float mx = -1e30f;
        #pragma unroll
        for (int d6 = 0; d6 < CPH; d6++){
            float knorm = fmaxf(sqrtf(a[42 + d6]), 1e-12f);
            float v = a[c6*CPH + d6] / (qnorm*knorm) * temp[h];
            s[d6] = v; mx = fmaxf(mx, v);
        }
        float sum = 0.f;
        #pragma unroll
        for (int d6 = 0; d6 < CPH; d6++){ s[d6] = expf(s[d6]-mx); sum += s[d6]; }
        float inv = 1.f/sum;
        #pragma unroll
        for (int d6 = 0; d6 < CPH; d6++)
            attn_s[(b*HEADS + h)*36 + c6*CPH + d6] = s[d6]*inv;
    }
    __syncthreads();
    for (int e = t; e < BATCH*DIM*DIM; e += blockDim.x){
        int b = e/(DIM*DIM), rem = e%(DIM*DIM), o = rem/DIM, d = rem%DIM;
        int h = d/CPH, d6 = d%CPH;
        float s = 0.f;
        #pragma unroll
        for (int c6 = 0; c6 < CPH; c6++)
            s += Wout[o*DIM + h*CPH + c6] * attn_s[(b*HEADS + h)*36 + c6*CPH + d6];
        g_meff[e] = s;
    }
}

// depthwise 3x3 for v channels -> g_v (unchanged)
__global__ __launch_bounds__(256, 2) void v_conv_kernel(const float* __restrict__ Wkv2){
    __shared__ float wv[DIM*9];
    const int tid = threadIdx.x;
    for (int t = tid; t < DIM*9; t += 256)
        wv[t] = Wkv2[(DIM + t/9)*27 + 9 + (t%9)];
    __syncthreads();

    const int lane = tid & 31;
    const int w    = tid >> 5;
    const int b    = blockIdx.z;
    const int x0   = blockIdx.x*32;
    const int x    = x0 + lane;
    const int yb   = blockIdx.y*8;
    const bool xm = (x > 0), xp = (x < WW-1);
    const bool fast = (x0 > 0) && (x0 + 32 < WW) && (yb > 0) && (yb + 9 < HH);

    const float* vbase = g_pwkv + (size_t)b*2*DIM*NPIX + (size_t)DIM*NPIX;
    float* vo = g_v + (size_t)b*DIM*NPIX;
    #pragma unroll
    for (int c6 = 0; c6 < CPH; c6++){
        int c = w*CPH + c6;
        float o[8];
        winconv<10>(vbase + (size_t)c*NPIX, x, xm, xp, yb - 1, fast, &wv[c*9], o);
        #pragma unroll
        for (int i = 0; i < 8; i++)
            vo[(size_t)c*NPIX + (size_t)(yb + i)*WW + x] = o[i];
    }
}

// ---------------- launch ----------------
extern "C" void kernel_launch(void* const* d_in, const int* in_sizes, int n_in,
                              void* d_out, int out_size){
    const float* img  = (const float*)d_in[0];
    const float* evs  = (const float*)d_in[1];
    const float* Wq1  = (const float*)d_in[2];
    const float* Wq2  = (const float*)d_in[3];
    const float* Wkv1 = (const float*)d_in[4];
    const float* Wkv2 = (const float*)d_in[5];
    const float* Wout = (const float*)d_in[6];
    const float* temp = (const float*)d_in[7];
    float* out = (float*)d_out;

    float *pwq, *pwkv, *vbuf, *meff;
    cudaGetSymbolAddress((void**)&pwq,  g_pwq);
    cudaGetSymbolAddress((void**)&pwkv, g_pwkv);
    cudaGetSymbolAddress((void**)&vbuf, g_v);
    cudaGetSymbolAddress((void**)&meff, g_meff);

    static cudaStream_t s2 = nullptr;
    static cudaEvent_t  evF = nullptr, evK = nullptr, evV = nullptr;
    if (s2 == nullptr){
        cudaStreamCreateWithFlags(&s2, cudaStreamNonBlocking);
        cudaEventCreateWithFlags(&evF, cudaEventDisableTiming);
        cudaEventCreateWithFlags(&evK, cudaEventDisableTiming);
        cudaEventCreateWithFlags(&evV, cudaEventDisableTiming);
    }

    const int smem_pw   = (48*PXS + 48*49)*4;   // 84,672 B
    const int smem_pw96 = (48*PXS + 96*49)*4;   // 94,080 B
    cudaFuncSetAttribute(pw_mma_kernel,   cudaFuncAttributeMaxDynamicSharedMemorySize, smem_pw);
    cudaFuncSetAttribute(pw_mma96_kernel, cudaFuncAttributeMaxDynamicSharedMemorySize, smem_pw96);

    zero_acc_kernel<<<3, 256>>>();

    cudaEventRecord(evF, 0);
    cudaStreamWaitEvent(s2, evF, 0);

    dim3 gpw(NPIX/PXB, BATCH);
    // stream B: fused 96-oc img pointwise (k+v), then v depthwise conv
    pw_mma96_kernel<<<gpw, 384, smem_pw96, s2>>>(img, Wkv1, pwkv);
    cudaEventRecord(evK, s2);
    dim3 gvc(WW/32, HH/8, BATCH);
    v_conv_kernel<<<gvc, 256, 0, s2>>>(Wkv2);
    cudaEventRecord(evV, s2);

    // main: evs pw, then qk (needs k), attn, final GEMM (needs g_v)
    pw_mma_kernel<<<gpw, 384, smem_pw>>>(evs, Wq1, pwq, DIM, DIM, 0);
    cudaStreamWaitEvent(0, evK, 0);

    dim3 gqk(WW/32, HH/128, BATCH*HEADS);
    qk_gram_kernel<<<gqk, 256>>>(Wq2, Wkv2);

    attn_kernel<<<1, 256>>>(Wout, temp);

    cudaStreamWaitEvent(0, evV, 0);
    pw_mma_kernel<<<gpw, 384, smem_pw>>>(vbuf, meff, out, DIM, DIM, DIM*DIM);
}

// round 13
// speedup vs baseline: 1.1163x; 1.0425x over previous
#include <cuda_runtime.h>
#include <cuda_fp16.h>
#include <math.h>

#define BATCH 2
#define DIM   48
#define HEADS 8
#define CPH   6
#define HH    384
#define WW    384
#define NPIX  (HH*WW)

#define PXB  384         // pixels per pw block
#define PXS  392         // padded smem stride (floats)
#define PXS2 400         // padded smem stride (halfs) for half-input GEMM

// ---------------- scratch ----------------
__device__ float  g_pwq [BATCH*DIM*NPIX];     // 56.6 MB
__device__ float  g_pwkv[BATCH*2*DIM*NPIX];   // 113 MB (k: 0..47, v: 48..95)
__device__ __half g_v   [BATCH*DIM*NPIX];     // 28.3 MB (dw-conv'd v, fp16)
__device__ float  g_acc [BATCH*HEADS*48];
__device__ float  g_meff[BATCH*DIM*DIM];

// ---------------- helpers ----------------
__device__ __forceinline__ void cpa16(unsigned int dst, const void* src){
    asm volatile("cp.async.cg.shared.global [%0], [%1], 16;" :: "r"(dst), "l"(src) : "memory");
}
__device__ __forceinline__ void cpa_commit(){
    asm volatile("cp.async.commit_group;" ::: "memory");
}
template<int N>
__device__ __forceinline__ void cpa_wait(){
    asm volatile("cp.async.wait_group %0;" :: "n"(N) : "memory");
}
__device__ __forceinline__ unsigned int f2tf32(float x){
    unsigned int u;
    asm("cvt.rna.tf32.f32 %0, %1;" : "=r"(u) : "f"(x));
    return u;
}
__device__ __forceinline__ void mma_tf32(float* d,
                                         const unsigned int* a,
                                         unsigned int b0, unsigned int b1){
    asm volatile(
        "mma.sync.aligned.m16n8k8.row.col.f32.tf32.tf32.f32 "
        "{%0,%1,%2,%3}, {%4,%5,%6,%7}, {%8,%9}, {%0,%1,%2,%3};"
        : "+f"(d[0]), "+f"(d[1]), "+f"(d[2]), "+f"(d[3])
        : "r"(a[0]), "r"(a[1]), "r"(a[2]), "r"(a[3]), "r"(b0), "r"(b1));
}

// Upfront-window depthwise conv (global-memory, scalar)
template<int R>
__device__ __forceinline__ void winconv(const float* __restrict__ chan, int x,
                                        bool xm, bool xp, int ytop, bool fast,
                                        const float* __restrict__ wr, float* out){
    float v[R][3];
    if (fast){
        const float* rp = chan + (size_t)ytop*WW + x;
        #pragma unroll
        for (int r = 0; r < R; r++){
            v[r][0] = __ldg(rp + r*WW - 1);
            v[r][1] = __ldg(rp + r*WW    );
            v[r][2] = __ldg(rp + r*WW + 1);
        }
    } else {
        int xl = max(x-1, 0), xr = min(x+1, WW-1);
        #pragma unroll
        for (int r = 0; r < R; r++){
            int yy = ytop + r; bool yok = (yy >= 0 && yy < HH);
            const float* rp = chan + (size_t)(yok ? yy : 0)*WW;
            v[r][0] = (yok && xm) ? __ldg(rp + xl) : 0.f;
            v[r][1] =  yok        ? __ldg(rp + x ) : 0.f;
            v[r][2] = (yok && xp) ? __ldg(rp + xr) : 0.f;
        }
    }
    #pragma unroll
    for (int i = 0; i < R-2; i++){
        out[i] = wr[0]*v[i  ][0] + wr[1]*v[i  ][1] + wr[2]*v[i  ][2]
               + wr[3]*v[i+1][0] + wr[4]*v[i+1][1] + wr[5]*v[i+1][2]
               + wr[6]*v[i+2][0] + wr[7]*v[i+2][1] + wr[8]*v[i+2][2];
    }
}

// ---------------- kernels ----------------
__global__ void zero_acc_kernel(){
    int t = blockIdx.x*blockDim.x + threadIdx.x;
    if (t < BATCH*HEADS*48) g_acc[t] = 0.f;
}

// 48-oc tf32 pw GEMM, fp32 input (evs pw + img k/v halves).
__global__ __launch_bounds__(384, 2) void pw_mma_kernel(const float* __restrict__ in,
                                                        const float* __restrict__ W,
                                                        float* __restrict__ out,
                                                        int inBC, int outBC){
    extern __shared__ float dsm[];
    float* xs = dsm;                                           // 48 x PXS
    unsigned int* wsm = (unsigned int*)(dsm + 48*PXS);         // 48 x 49

    const int tid = threadIdx.x;
    const int b   = blockIdx.y;

    const int base = blockIdx.x*PXB;
    const float* inp = in + (size_t)b*inBC*NPIX + base;
    const unsigned int xsu = (unsigned int)__cvta_generic_to_shared(xs);
    #pragma unroll
    for (int r = 0; r < 12; r++){
        int e  = tid + r*384;
        int ic = e/96, q = e%96;
        cpa16(xsu + (unsigned int)((ic*PXS + q*4)*4),
              inp + (size_t)ic*NPIX + q*4);
    }
    cpa_commit();

    #pragma unroll
    for (int r = 0; r < 6; r++){
        int t = tid + r*384;
        int oc = t/48, ic = t%48;
        wsm[oc*49 + ic] = f2tf32(W[t]);
    }

    cpa_wait<0>();
    __syncthreads();

    const int w    = tid >> 5;
    const int lane = tid & 31;
    const int mt   = w % 3;
    const int ng   = w / 3;
    const int gid  = lane >> 2;
    const int tig  = lane & 3;

    unsigned int a[6][4];
    #pragma unroll
    for (int ks = 0; ks < 6; ks++){
        int r0 = mt*16 + gid, k0 = ks*8 + tig;
        a[ks][0] = wsm[ r0     *49 + k0    ];
        a[ks][1] = wsm[(r0 + 8)*49 + k0    ];
        a[ks][2] = wsm[ r0     *49 + k0 + 4];
        a[ks][3] = wsm[(r0 + 8)*49 + k0 + 4];
    }

    float* op = out + (size_t)b*outBC*NPIX + base;
    const int r0 = mt*16 + gid;

    #pragma unroll
    for (int i = 0; i < 12; i++){
        const int px0 = (ng*12 + i)*8;
        float d[4] = {0.f, 0.f, 0.f, 0.f};
        #pragma unroll
        for (int ks = 0; ks < 6; ks++){
            unsigned int b0 = f2tf32(xs[(ks*8 + tig    )*PXS + px0 + gid]);
            unsigned int b1 = f2tf32(xs[(ks*8 + tig + 4)*PXS + px0 + gid]);
            mma_tf32(d, a[ks], b0, b1);
        }
        *reinterpret_cast<float2*>(op + (size_t)r0*NPIX     + px0 + tig*2) = make_float2(d[0], d[1]);
        *reinterpret_cast<float2*>(op + (size_t)(r0+8)*NPIX + px0 + tig*2) = make_float2(d[2], d[3]);
    }
}

// 48-oc tf32 pw GEMM, fp16 input (the final out = Meff * v GEMM).
// Per-batch weights: W + b*2304.
__global__ __launch_bounds__(384, 2) void pw_mma_h_kernel(const __half* __restrict__ in,
                                                          const float* __restrict__ W,
                                                          float* __restrict__ out){
    extern __shared__ float dsm[];
    __half* xs = (__half*)dsm;                                  // 48 x PXS2 halfs
    unsigned int* wsm = (unsigned int*)(dsm + (48*PXS2)/2);     // 48 x 49

    const int tid = threadIdx.x;
    const int b   = blockIdx.y;
    const float* Wb = W + b*DIM*DIM;

    const int base = blockIdx.x*PXB;
    const __half* inp = in + (size_t)b*DIM*NPIX + base;
    const unsigned int xsu = (unsigned int)__cvta_generic_to_shared(xs);
    // 48 ch x 48 chunks of 8 halfs (16B) = 2304 chunks, 6 per thread
    #pragma unroll
    for (int r = 0; r < 6; r++){
        int e  = tid + r*384;
        int ic = e/48, q = e%48;
        cpa16(xsu + (unsigned int)((ic*PXS2 + q*8)*2),
              inp + (size_t)ic*NPIX + q*8);
    }
    cpa_commit();

    #pragma unroll
    for (int r = 0; r < 6; r++){
        int t = tid + r*384;
        int oc = t/48, ic = t%48;
        wsm[oc*49 + ic] = f2tf32(Wb[t]);
    }

    cpa_wait<0>();
    __syncthreads();

    const int w    = tid >> 5;
    const int lane = tid & 31;
    const int mt   = w % 3;
    const int ng   = w / 3;
    const int gid  = lane >> 2;
    const int tig  = lane & 3;

    unsigned int a[6][4];
    #pragma unroll
    for (int ks = 0; ks < 6; ks++){
        int r0 = mt*16 + gid, k0 = ks*8 + tig;
        a[ks][0] = wsm[ r0     *49 + k0    ];
        a[ks][1] = wsm[(r0 + 8)*49 + k0    ];
        a[ks][2] = wsm[ r0     *49 + k0 + 4];
        a[ks][3] = wsm[(r0 + 8)*49 + k0 + 4];
    }

    float* op = out + (size_t)b*DIM*NPIX + base;
    const int r0 = mt*16 + gid;

    #pragma unroll
    for (int i = 0; i < 12; i++){
        const int px0 = (ng*12 + i)*8;
        float d[4] = {0.f, 0.f, 0.f, 0.f};
        #pragma unroll
        for (int ks = 0; ks < 6; ks++){
            unsigned int b0 = f2tf32(__half2float(xs[(ks*8 + tig    )*PXS2 + px0 + gid]));
            unsigned int b1 = f2tf32(__half2float(xs[(ks*8 + tig + 4)*PXS2 + px0 + gid]));
            mma_tf32(d, a[ks], b0, b1);
        }
        *reinterpret_cast<float2*>(op + (size_t)r0*NPIX     + px0 + tig*2) = make_float2(d[0], d[1]);
        *reinterpret_cast<float2*>(op + (size_t)(r0+8)*NPIX + px0 + tig*2) = make_float2(d[2], d[3]);
    }
}

// q,k depthwise 3x3 + Gram/norm. One (b,h) per block; block covers 32x128 px.
// (PROTECTED R5/R10 version)
__global__ __launch_bounds__(256, 2) void qk_gram_kernel(const float* __restrict__ Wq2,
                                                         const float* __restrict__ Wkv2){
    __shared__ float wq[CPH*9], wk[CPH*9];
    __shared__ float accs[48];
    const int tid = threadIdx.x;
    const int bh  = blockIdx.z;
    const int b   = bh >> 3, h = bh & 7;
    if (tid < CPH*9){
        int c6 = tid/9, t = tid%9;
        wq[tid] = Wq2[(h*CPH + c6)*27 + 9 + t];
    } else if (tid >= 64 && tid < 64 + CPH*9){
        int e = tid - 64, c6 = e/9, t = e%9;
        wk[e] = Wkv2[(h*CPH + c6)*27 + 9 + t];
    } else if (tid >= 128 && tid < 176){
        accs[tid - 128] = 0.f;
    }
    __syncthreads();

    const int lane = tid & 31;
    const int w    = tid >> 5;
    const int x0   = blockIdx.x*32;
    const int x    = x0 + lane;
    const bool xm = (x > 0), xp = (x < WW-1);
    const bool xfast = (x0 > 0) && (x0 + 32 < WW);

    const float* qbase = g_pwq  + (size_t)b*DIM*NPIX   + (size_t)h*CPH*NPIX;
    const float* kbase = g_pwkv + (size_t)b*2*DIM*NPIX + (size_t)h*CPH*NPIX;

    float G[36], qn[CPH], kn[CPH];
    #pragma unroll
    for (int i = 0; i < 36; i++) G[i] = 0.f;
    #pragma unroll
    for (int i = 0; i < CPH; i++){ qn[i] = 0.f; kn[i] = 0.f; }

    #pragma unroll 1
    for (int t4 = 0; t4 < 4; t4++){
        const int y0   = blockIdx.y*128 + t4*32 + w*4;
        const int ytop = y0 - 1;
        const bool fast = xfast && (ytop >= 0) && (ytop + 5 < HH);

        float ka[CPH][4];
        #pragma unroll
        for (int c6 = 0; c6 < CPH; c6++){
            float o[4];
            winconv<6>(kbase + (size_t)c6*NPIX, x, xm, xp, ytop, fast, &wk[c6*9], o);
            #pragma unroll
            for (int i = 0; i < 4; i++){ ka[c6][i] = o[i]; kn[c6] += o[i]*o[i]; }
        }
        #pragma unroll
        for (int c6 = 0; c6 < CPH; c6++){
            float o[4];
            winconv<6>(qbase + (size_t)c6*NPIX, x, xm, xp, ytop, fast, &wq[c6*9], o);
            #pragma unroll
            for (int i = 0; i < 4; i++) qn[c6] += o[i]*o[i];
            #pragma unroll
            for (int d6 = 0; d6 < CPH; d6++)
                G[c6*CPH + d6] += o[0]*ka[d6][0] + o[1]*ka[d6][1]
                                + o[2]*ka[d6][2] + o[3]*ka[d6][3];
        }
    }

    #pragma unroll
    for (int j = 0; j < 36; j++){
        float v = G[j];
        #pragma unroll
        for (int o = 16; o; o >>= 1) v += __shfl_xor_sync(0xffffffffu, v, o);
        if (lane == 0) atomicAdd(&accs[j], v);
    }
    #pragma unroll
    for (int j = 0; j < CPH; j++){
        float v = qn[j];
        #pragma unroll
        for (int o = 16; o; o >>= 1) v += __shfl_xor_sync(0xffffffffu, v, o);
        if (lane == 0) atomicAdd(&accs[36 + j], v);
        float u = kn[j];
        #pragma unroll
        for (int o = 16; o; o >>= 1) u += __shfl_xor_sync(0xffffffffu, u, o);
        if (lane == 0) atomicAdd(&accs[42 + j], u);
    }
    __syncthreads();
    if (tid < 48) atomicAdd(&g_acc[(b*HEADS + h)*48 + tid], accs[tid]);
}

// softmax + fold Wout -> Meff[b] (48x48)
__global__ void attn_kernel(const float* __restrict__ Wout,
                            const float* __restrict__ temp){
    __shared__ float attn_s[BATCH*HEADS*36];
    int t = threadIdx.x;
    if (t < BATCH*HEADS*CPH){
        int b  = t/(HEADS*CPH);
        int h  = (t/CPH)%HEADS;
        int c6 = t%CPH;
        const float* a = g_acc + (b*HEADS + h)*48;
        float qnorm = fmaxf(sqrtf(a[36 + c6]), 1e-12f);
        float s[CPH];
        float mx = -1e30f;
        #pragma unroll
        for (int d6 = 0; d6 < CPH; d6++){
            float knorm = fmaxf(sqrtf(a[42 + d6]), 1e-12f);
            float v = a[c6*CPH + d6] / (qnorm*knorm) * temp[h];
            s[d6] = v; mx = fmaxf(mx, v);
        }
        float sum = 0.f;
        #pragma unroll
        for (int d6 = 0; d6 < CPH; d6++){ s[d6] = expf(s[d6]-mx); sum += s[d6]; }
        float inv = 1.f/sum;
        #pragma unroll
        for (int d6 = 0; d6 < CPH; d6++)
            attn_s[(b*HEADS + h)*36 + c6*CPH + d6] = s[d6]*inv;
    }
    __syncthreads();
    for (int e = t; e < BATCH*DIM*DIM; e += blockDim.x){
        int b = e/(DIM*DIM), rem = e%(DIM*DIM), o = rem/DIM, d = rem%DIM;
        int h = d/CPH, d6 = d%CPH;
        float s = 0.f;
        #pragma unroll
        for (int c6 = 0; c6 < CPH; c6++)
            s += Wout[o*DIM + h*CPH + c6] * attn_s[(b*HEADS + h)*36 + c6*CPH + d6];
        g_meff[e] = s;
    }
}

// depthwise 3x3 for v channels -> g_v (fp16 store)
__global__ __launch_bounds__(256, 2) void v_conv_kernel(const float* __restrict__ Wkv2){
    __shared__ float wv[DIM*9];
    const int tid = threadIdx.x;
    for (int t = tid; t < DIM*9; t += 256)
        wv[t] = Wkv2[(DIM + t/9)*27 + 9 + (t%9)];
    __syncthreads();

    const int lane = tid & 31;
    const int w    = tid >> 5;
    const int b    = blockIdx.z;
    const int x0   = blockIdx.x*32;
    const int x    = x0 + lane;
    const int yb   = blockIdx.y*8;
    const bool xm = (x > 0), xp = (x < WW-1);
    const bool fast = (x0 > 0) && (x0 + 32 < WW) && (yb > 0) && (yb + 9 < HH);

    const float* vbase = g_pwkv + (size_t)b*2*DIM*NPIX + (size_t)DIM*NPIX;
    __half* vo = g_v + (size_t)b*DIM*NPIX;
    #pragma unroll
    for (int c6 = 0; c6 < CPH; c6++){
        int c = w*CPH + c6;
        float o[8];
        winconv<10>(vbase + (size_t)c*NPIX, x, xm, xp, yb - 1, fast, &wv[c*9], o);
        #pragma unroll
        for (int i = 0; i < 8; i++)
            vo[(size_t)c*NPIX + (size_t)(yb + i)*WW + x] = __float2half(o[i]);
    }
}

// ---------------- launch ----------------
extern "C" void kernel_launch(void* const* d_in, const int* in_sizes, int n_in,
                              void* d_out, int out_size){
    const float* img  = (const float*)d_in[0];
    const float* evs  = (const float*)d_in[1];
    const float* Wq1  = (const float*)d_in[2];
    const float* Wq2  = (const float*)d_in[3];
    const float* Wkv1 = (const float*)d_in[4];
    const float* Wkv2 = (const float*)d_in[5];
    const float* Wout = (const float*)d_in[6];
    const float* temp = (const float*)d_in[7];
    float* out = (float*)d_out;

    float  *pwq, *pwkv, *meff;
    __half *vbuf;
    cudaGetSymbolAddress((void**)&pwq,  g_pwq);
    cudaGetSymbolAddress((void**)&pwkv, g_pwkv);
    cudaGetSymbolAddress((void**)&vbuf, g_v);
    cudaGetSymbolAddress((void**)&meff, g_meff);

    static cudaStream_t s2 = nullptr;
    static cudaEvent_t  evF = nullptr, evK = nullptr, evV = nullptr;
    if (s2 == nullptr){
        cudaStreamCreateWithFlags(&s2, cudaStreamNonBlocking);
        cudaEventCreateWithFlags(&evF, cudaEventDisableTiming);
        cudaEventCreateWithFlags(&evK, cudaEventDisableTiming);
        cudaEventCreateWithFlags(&evV, cudaEventDisableTiming);
    }

    const int smem_pw  = (48*PXS  + 48*49)*4;        // 84,672 B
    const int smem_pwh = (48*PXS2)*2 + 48*49*4;      // 47,808 B
    cudaFuncSetAttribute(pw_mma_kernel,   cudaFuncAttributeMaxDynamicSharedMemorySize, smem_pw);
    cudaFuncSetAttribute(pw_mma_h_kernel, cudaFuncAttributeMaxDynamicSharedMemorySize, smem_pwh);

    zero_acc_kernel<<<3, 256>>>();

    cudaEventRecord(evF, 0);
    cudaStreamWaitEvent(s2, evF, 0);

    dim3 gpw(NPIX/PXB, BATCH);
    // stream B: k-half of img pw (early evK), then v-half + v depthwise conv
    pw_mma_kernel<<<gpw, 384, smem_pw, s2>>>(img, Wkv1, pwkv, DIM, 2*DIM);
    cudaEventRecord(evK, s2);
    pw_mma_kernel<<<gpw, 384, smem_pw, s2>>>(img, Wkv1 + DIM*DIM,
                                             pwkv + (size_t)DIM*NPIX, DIM, 2*DIM);
    dim3 gvc(WW/32, HH/8, BATCH);
    v_conv_kernel<<<gvc, 256, 0, s2>>>(Wkv2);
    cudaEventRecord(evV, s2);

    // main: evs pw, then qk (needs k), attn, final GEMM (needs g_v)
    pw_mma_kernel<<<gpw, 384, smem_pw>>>(evs, Wq1, pwq, DIM, DIM);
    cudaStreamWaitEvent(0, evK, 0);

    dim3 gqk(WW/32, HH/128, BATCH*HEADS);
    qk_gram_kernel<<<gqk, 256>>>(Wq2, Wkv2);

    attn_kernel<<<1, 256>>>(Wout, temp);

    cudaStreamWaitEvent(0, evV, 0);
    pw_mma_h_kernel<<<gpw, 384, smem_pwh>>>(vbuf, meff, out);
}